// round 15
// baseline (speedup 1.0000x reference)
#include <cuda_runtime.h>
#include <cstdint>
#include <cstddef>

#define BATCH   4
#define NNODE   4096
#define DF      128
#define UNITS   128
#define TILE_R  128
#define SC      128                 // s rows per chunk
#define NCHUNK  (NNODE / SC)        // 32
#define ADJ_STRIDE 132              // floats per adj smem row: 128 + 4 pad (528 B)
#define ADJ_ST_FLOATS (SC * ADJ_STRIDE)   // 16896 floats / stage

// Combined weights (device scratch; no cudaMalloc allowed)
//   g_Wap[p*256 + 2*c + e] = Wa[2p+e][c]   (pair p = k/2, e = k&1)
__device__ float g_Wap[DF * UNITS];  // W1 + Wr@W2, pair-interleaved
__device__ float g_Wbp[DF * UNITS];  // Ws@W2, pair-interleaved
__device__ float g_Wr2[DF * UNITS];  // Wr@W2 row-major (deg==0 fixup only)

// ---------------------------------------------------------------------------
// Phase 0: weight prep. 128 blocks x 128 threads. Block i computes row i.
// ---------------------------------------------------------------------------
__global__ void prep_weights(const float* __restrict__ Wmsg,
                             const float* __restrict__ Wupd) {
    __shared__ float ws[DF];
    __shared__ float wr[DF];
    const int i = blockIdx.x;
    const int j = threadIdx.x;
    ws[j] = Wmsg[i * UNITS + j];
    wr[j] = Wmsg[(DF + i) * UNITS + j];
    __syncthreads();
    float sa = 0.f, sr = 0.f;
#pragma unroll 4
    for (int k = 0; k < DF; ++k) {
        const float w2 = Wupd[(DF + k) * UNITS + j];
        sa = fmaf(ws[k], w2, sa);
        sr = fmaf(wr[k], w2, sr);
    }
    const int pidx = (i >> 1) * 256 + (j << 1) + (i & 1);
    g_Wbp[pidx] = sa;
    g_Wr2[i * UNITS + j] = sr;
    g_Wap[pidx] = Wupd[i * UNITS + j] + sr;
}

// ---------------------------------------------------------------------------
// PTX helpers
// ---------------------------------------------------------------------------
__device__ __forceinline__ uint32_t smem_u32(const void* p) {
    uint32_t a;
    asm("{ .reg .u64 t; cvta.to.shared.u64 t, %1; cvt.u32.u64 %0, t; }"
        : "=r"(a) : "l"(p));
    return a;
}
__device__ __forceinline__ void mbar_init(uint32_t mbar, uint32_t cnt) {
    asm volatile("mbarrier.init.shared.b64 [%0], %1;" :: "r"(mbar), "r"(cnt) : "memory");
}
__device__ __forceinline__ void mbar_expect_tx(uint32_t mbar, uint32_t bytes) {
    asm volatile("mbarrier.arrive.expect_tx.shared.b64 _, [%0], %1;"
                 :: "r"(mbar), "r"(bytes) : "memory");
}
__device__ __forceinline__ void mbar_arrive(uint32_t mbar) {
    asm volatile("mbarrier.arrive.shared.b64 _, [%0];" :: "r"(mbar) : "memory");
}
__device__ __forceinline__ void mbar_wait(uint32_t mbar, uint32_t parity) {
    uint32_t done;
    asm volatile(
        "{ .reg .pred p; mbarrier.try_wait.parity.acquire.cta.shared::cta.b64 p, [%1], %2;"
        " selp.b32 %0,1,0,p; }"
        : "=r"(done) : "r"(mbar), "r"(parity) : "memory");
    if (!done) {
        asm volatile(
            "{ .reg .pred P1;\n"
            "WL_%=: mbarrier.try_wait.parity.acquire.cta.shared::cta.b64 P1, [%0], %1, 0x989680;\n"
            "@P1 bra.uni WD_%=;\n"
            "bra.uni WL_%=;\n"
            "WD_%=: }"
            :: "r"(mbar), "r"(parity) : "memory");
    }
}
__device__ __forceinline__ void bulk_g2s(uint32_t dst, const void* src,
                                         uint32_t bytes, uint32_t mbar) {
    asm volatile(
        "cp.async.bulk.shared::cta.global.mbarrier::complete_tx::bytes [%0], [%1], %2, [%3];"
        :: "r"(dst), "l"(src), "r"(bytes), "r"(mbar) : "memory");
}
__device__ __forceinline__ void fma2(unsigned long long& d, unsigned long long a,
                                     unsigned long long b) {
    asm("fma.rn.f32x2 %0, %1, %2, %0;" : "+l"(d) : "l"(a), "l"(b));
}

// ---------------------------------------------------------------------------
// Main fused kernel. grid (32, 4), 1024 threads, 1 CTA/SM.
// smem: 3 adj stages of SC*132 floats = 202,752 B
// mbarriers: full[3] @ +0/+8/+16 (tx), empty[3] @ +24/+32/+40 (count 32),
//            mbX @ +48 (count 128)
// ---------------------------------------------------------------------------
extern __shared__ float smem[];

__global__ __launch_bounds__(1024, 1)
void mpnn_main(const float* __restrict__ x,
               const float* __restrict__ adj,
               float* __restrict__ out) {
    __shared__ __align__(8) unsigned long long mb[7];
    __shared__ float degs[TILE_R];

    const int b   = blockIdx.y;
    const int r0  = blockIdx.x * TILE_R;
    const int tid = threadIdx.x;
    const int w    = tid >> 5;   // warp 0..31: owns r-cols r0+4w .. 4w+3
    const int lane = tid & 31;

    const float* adjb = adj + (size_t)b * NNODE * NNODE;
    const float* xb   = x   + (size_t)b * NNODE * DF;

    const uint32_t mb_base = smem_u32(&mb[0]);
    if (tid == 0) {
        mbar_init(mb_base + 0,  1);    // full0 (tx-driven)
        mbar_init(mb_base + 8,  1);    // full1
        mbar_init(mb_base + 16, 1);    // full2
        mbar_init(mb_base + 24, 32);   // empty0 (one arrive per warp)
        mbar_init(mb_base + 32, 32);   // empty1
        mbar_init(mb_base + 40, 32);   // empty2
        mbar_init(mb_base + 48, 128);  // x staging
    }
    __syncthreads();

    // producer (warp 0): fill stage of chunk c with 128 row copies (4 per lane)
    auto issue_chunk = [&](int c, bool wait_empty) {
        const int st = c % 3;
        const uint32_t fullb = mb_base + st * 8;
        if (wait_empty) mbar_wait(mb_base + 24 + st * 8, ((c / 3) - 1) & 1);
        if (lane == 0) mbar_expect_tx(fullb, 128 * 512);
        __syncwarp();
#pragma unroll
        for (int t = 0; t < 4; ++t) {
            const int row = (t << 5) + lane;
            bulk_g2s(smem_u32(&smem[(size_t)st * ADJ_ST_FLOATS +
                                    (size_t)row * ADJ_STRIDE]),
                     adjb + (size_t)(c * SC + row) * NNODE + r0, 512, fullb);
        }
    };

    float acc[4][4] = {};
    int   dcnt[4]   = {0, 0, 0, 0};

    // -------- phase 1: warp-decoupled 3-stage pipeline, per-r ballot scan --------
    if (w == 0) {
        issue_chunk(0, false);
        issue_chunk(1, false);
        issue_chunk(2, false);
    }

    for (int c = 0; c < NCHUNK; ++c) {
        const int st = c % 3;
        mbar_wait(mb_base + st * 8, (c / 3) & 1);   // per-warp full wait

        const float* cur = smem + (size_t)st * ADJ_ST_FLOATS;
        const int s_chunk = c << 7;

#pragma unroll
        for (int sb = 0; sb < SC; sb += 32) {
            const float4 av = *reinterpret_cast<const float4*>(
                &cur[(sb + lane) * ADJ_STRIDE + (w << 2)]);
            const int s_base = s_chunk + sb;

            // set bit == adj entry is EXACTLY 1.0 -> aggregate is a plain add
            unsigned m0 = __ballot_sync(0xffffffffu, av.x != 0.0f);
            unsigned m1 = __ballot_sync(0xffffffffu, av.y != 0.0f);
            unsigned m2 = __ballot_sync(0xffffffffu, av.z != 0.0f);
            unsigned m3 = __ballot_sync(0xffffffffu, av.w != 0.0f);
            dcnt[0] += __popc(m0);
            dcnt[1] += __popc(m1);
            dcnt[2] += __popc(m2);
            dcnt[3] += __popc(m3);

#define SCAN_COMP(MASK, RP)                                                          \
            while (MASK) {                                                           \
                const int i = __ffs(MASK) - 1; MASK &= MASK - 1;                     \
                const float4 xv = *reinterpret_cast<const float4*>(                  \
                    &xb[(size_t)(s_base + i) * DF + (lane << 2)]);                   \
                acc[RP][0] += xv.x; acc[RP][1] += xv.y;                              \
                acc[RP][2] += xv.z; acc[RP][3] += xv.w;                              \
            }
            SCAN_COMP(m0, 0)
            SCAN_COMP(m1, 1)
            SCAN_COMP(m2, 2)
            SCAN_COMP(m3, 3)
#undef SCAN_COMP
        }

        if (lane == 0) mbar_arrive(mb_base + 24 + st * 8);   // release stage
        if (w == 0 && c + 3 < NCHUNK) issue_chunk(c + 3, true);
    }

    // -------- phase boundary (single block-wide sync) --------
    __syncthreads();

    float* xsm = smem;                        // [128][128]
    float* zsm = smem + TILE_R * DF;          // [128][128]

    // stage this block's own x rows (contiguous 512 B per row) via bulk copy
    if (tid < 128) {
        mbar_expect_tx(mb_base + 48, 512);
        bulk_g2s(smem_u32(&xsm[(size_t)tid * DF]),
                 xb + (size_t)(r0 + tid) * DF, 512, mb_base + 48);
    }

    // dcnt is warp-uniform (popc of full ballots)
#pragma unroll
    for (int rp = 0; rp < 4; ++rp) {
        const int r = (w << 2) + rp;
        const float d = (float)dcnt[rp];
        const float inv = (dcnt[rp] > 0) ? (1.0f / d) : 0.0f;
        float4 zv;
        zv.x = acc[rp][0] * inv; zv.y = acc[rp][1] * inv;
        zv.z = acc[rp][2] * inv; zv.w = acc[rp][3] * inv;
        *reinterpret_cast<float4*>(&zsm[(size_t)r * DF + (lane << 2)]) = zv;
        if (lane == 0) degs[r] = d;
    }

    mbar_wait(mb_base + 48, 0);
    __syncthreads();

    // -------- phase 2: out = xsm @ Wa + zsm @ Wb  (k-pair packed f32x2) --------
    const int rg  = w >> 2;                 // 0..7 -> rows 16*rg .. +16
    const int col = ((w & 3) << 5) + lane;  // 0..127

    unsigned long long cacc[16];
#pragma unroll
    for (int i = 0; i < 16; ++i) cacc[i] = 0ull;

#pragma unroll 1
    for (int pass = 0; pass < 2; ++pass) {
        const float* A  = pass ? zsm : xsm;
        const float* Wp = pass ? g_Wbp : g_Wap;
#pragma unroll 4
        for (int k = 0; k < DF; k += 4) {
            const unsigned long long w0 = *reinterpret_cast<const unsigned long long*>(
                &Wp[(size_t)(k >> 1) * 256 + (col << 1)]);
            const unsigned long long w1 = *reinterpret_cast<const unsigned long long*>(
                &Wp[(size_t)((k >> 1) + 1) * 256 + (col << 1)]);
#pragma unroll
            for (int i = 0; i < 16; ++i) {
                const ulonglong2 av = *reinterpret_cast<const ulonglong2*>(
                    &A[(size_t)(16 * rg + i) * DF + k]);   // warp-uniform broadcast
                fma2(cacc[i], av.x, w0);
                fma2(cacc[i], av.y, w1);
            }
        }
    }

    float* outb = out + ((size_t)b * NNODE + r0) * UNITS;
#pragma unroll
    for (int i = 0; i < 16; ++i) {
        const int r = 16 * rg + i;
        unsigned lo, hi;
        asm("mov.b64 {%0, %1}, %2;" : "=r"(lo), "=r"(hi) : "l"(cacc[i]));
        float o = __uint_as_float(lo) + __uint_as_float(hi);

        if (degs[r] == 0.0f) {
            // message term must be exactly zero: remove the x@Wr@W2 contribution
            float corr = 0.0f;
            for (int k = 0; k < DF; ++k)
                corr = fmaf(xsm[(size_t)r * DF + k], g_Wr2[k * UNITS + col], corr);
            o -= corr;
        }
        outb[(size_t)r * UNITS + col] = o;
    }
}

// ---------------------------------------------------------------------------
// Launch
// ---------------------------------------------------------------------------
extern "C" void kernel_launch(void* const* d_in, const int* in_sizes, int n_in,
                              void* d_out, int out_size) {
    (void)in_sizes; (void)n_in; (void)out_size;
    const float* x    = (const float*)d_in[0];
    const float* adj  = (const float*)d_in[1];
    const float* Wmsg = (const float*)d_in[2];
    const float* Wupd = (const float*)d_in[3];
    float* out = (float*)d_out;

    prep_weights<<<128, 128>>>(Wmsg, Wupd);

    const size_t shbytes = (size_t)3 * ADJ_ST_FLOATS * sizeof(float);  // 202752
    cudaFuncSetAttribute(mpnn_main, cudaFuncAttributeMaxDynamicSharedMemorySize,
                         (int)shbytes);
    mpnn_main<<<dim3(NNODE / TILE_R, BATCH), 1024, shbytes>>>(x, adj, out);
}

// round 16
// speedup vs baseline: 2.2724x; 2.2724x over previous
#include <cuda_runtime.h>
#include <cstdint>
#include <cstddef>

#define BATCH   4
#define NNODE   4096
#define DF      128
#define UNITS   128
#define TILE_R  128
#define SC      128                 // s rows per chunk
#define NCHUNK  (NNODE / SC)        // 32
#define ADJ_STRIDE 132              // floats per adj smem row: 128 + 4 pad (528 B)
#define ADJ_ST_FLOATS (SC * ADJ_STRIDE)   // 16896 floats / buffer
#define ZS      132                 // zsm row stride

// Combined weights (device scratch; no cudaMalloc allowed)
//   g_Wap[p*256 + 2*c + e] = Wa[2p+e][c]   (pair p = k/2, e = k&1)
__device__ float g_Wap[DF * UNITS];  // W1 + Wr@W2, pair-interleaved
__device__ float g_Wbp[DF * UNITS];  // Ws@W2, pair-interleaved
__device__ float g_Wr2[DF * UNITS];  // Wr@W2 row-major (deg==0 fixup only)

// ---------------------------------------------------------------------------
// Phase 0: weight prep. 128 blocks x 128 threads. Block i computes row i.
// ---------------------------------------------------------------------------
__global__ void prep_weights(const float* __restrict__ Wmsg,
                             const float* __restrict__ Wupd) {
    __shared__ float ws[DF];
    __shared__ float wr[DF];
    const int i = blockIdx.x;
    const int j = threadIdx.x;
    ws[j] = Wmsg[i * UNITS + j];
    wr[j] = Wmsg[(DF + i) * UNITS + j];
    __syncthreads();
    float sa = 0.f, sr = 0.f;
#pragma unroll 4
    for (int k = 0; k < DF; ++k) {
        const float w2 = Wupd[(DF + k) * UNITS + j];
        sa = fmaf(ws[k], w2, sa);
        sr = fmaf(wr[k], w2, sr);
    }
    const int pidx = (i >> 1) * 256 + (j << 1) + (i & 1);
    g_Wbp[pidx] = sa;
    g_Wr2[i * UNITS + j] = sr;
    g_Wap[pidx] = Wupd[i * UNITS + j] + sr;
}

// Packed f32x2 FMA: d = a*b + d  (both lanes)
__device__ __forceinline__ void fma2(unsigned long long& d, unsigned long long a,
                                     unsigned long long b) {
    asm("fma.rn.f32x2 %0, %1, %2, %0;" : "+l"(d) : "l"(a), "l"(b));
}

// ---------------------------------------------------------------------------
// Main fused kernel. grid (32, 4), 1024 threads, 1 CTA/SM.
// dynamic smem: 2 adj buffers of SC*132 floats = 135,168 B
// phase-2 overlay: xsm (stride 128) in buf0, zsm (stride 132) in buf1
// ---------------------------------------------------------------------------
extern __shared__ float smem[];

__global__ __launch_bounds__(1024, 1)
void mpnn_main(const float* __restrict__ x,
               const float* __restrict__ adj,
               float* __restrict__ out) {
    __shared__ float degs[TILE_R];

    const int b   = blockIdx.y;
    const int r0  = blockIdx.x * TILE_R;
    const int tid = threadIdx.x;
    const int w    = tid >> 5;   // warp 0..31: owns r-cols r0+4w .. 4w+3
    const int lane = tid & 31;

    const float* adjb = adj + (size_t)b * NNODE * NNODE;
    const float* xb   = x   + (size_t)b * NNODE * DF;

    // stage chunk c into buf[c&1] via coalesced LDG.128 -> STS.128.
    // warp `w` stages rows w, w+32, w+64, w+96 (512 B contiguous each).
    auto stage = [&](int c) {
        float* dst = smem + (size_t)(c & 1) * ADJ_ST_FLOATS;
        const float* src = adjb + (size_t)c * SC * NNODE + r0;
        const int col = lane << 2;
        const uint4 t0 = *(const uint4*)(src + (size_t)(w      ) * NNODE + col);
        const uint4 t1 = *(const uint4*)(src + (size_t)(w + 32 ) * NNODE + col);
        const uint4 t2 = *(const uint4*)(src + (size_t)(w + 64 ) * NNODE + col);
        const uint4 t3 = *(const uint4*)(src + (size_t)(w + 96 ) * NNODE + col);
        *(uint4*)&dst[(size_t)(w      ) * ADJ_STRIDE + col] = t0;
        *(uint4*)&dst[(size_t)(w + 32 ) * ADJ_STRIDE + col] = t1;
        *(uint4*)&dst[(size_t)(w + 64 ) * ADJ_STRIDE + col] = t2;
        *(uint4*)&dst[(size_t)(w + 96 ) * ADJ_STRIDE + col] = t3;
    };

    float acc[4][4] = {};
    int   dcnt[4]   = {0, 0, 0, 0};

    // -------- phase 1: LDG->STS double-buffered stream + per-r ballot scan ------
    stage(0);
    __syncthreads();

    for (int c = 0; c < NCHUNK; ++c) {
        if (c + 1 < NCHUNK) stage(c + 1);   // LDG latency hidden by scan below

        const float* cur = smem + (size_t)(c & 1) * ADJ_ST_FLOATS;
        const int s_chunk = c << 7;

#pragma unroll
        for (int sb = 0; sb < SC; sb += 32) {
            const float4 av = *reinterpret_cast<const float4*>(
                &cur[(sb + lane) * ADJ_STRIDE + (w << 2)]);
            const int s_base = s_chunk + sb;

            // set bit == adj entry is EXACTLY 1.0 -> aggregate is a plain add
            unsigned m0 = __ballot_sync(0xffffffffu, av.x != 0.0f);
            unsigned m1 = __ballot_sync(0xffffffffu, av.y != 0.0f);
            unsigned m2 = __ballot_sync(0xffffffffu, av.z != 0.0f);
            unsigned m3 = __ballot_sync(0xffffffffu, av.w != 0.0f);
            dcnt[0] += __popc(m0);
            dcnt[1] += __popc(m1);
            dcnt[2] += __popc(m2);
            dcnt[3] += __popc(m3);

#define SCAN_COMP(MASK, RP)                                                          \
            while (MASK) {                                                           \
                const int i = __ffs(MASK) - 1; MASK &= MASK - 1;                     \
                const float4 xv = *reinterpret_cast<const float4*>(                  \
                    &xb[(size_t)(s_base + i) * DF + (lane << 2)]);                   \
                acc[RP][0] += xv.x; acc[RP][1] += xv.y;                              \
                acc[RP][2] += xv.z; acc[RP][3] += xv.w;                              \
            }
            SCAN_COMP(m0, 0)
            SCAN_COMP(m1, 1)
            SCAN_COMP(m2, 2)
            SCAN_COMP(m3, 3)
#undef SCAN_COMP
        }
        __syncthreads();   // scan of buf[c&1] and stage of buf[(c+1)&1] complete
    }

    // -------- phase boundary: overlay smem with xsm (buf0) / zsm (buf1) --------
    float* xsm = smem;                        // [128][128]
    float* zsm = smem + ADJ_ST_FLOATS;        // [128][132]

    // stage this block's own x rows: same coalesced LDG->STS pattern
    {
        const float* src = xb + (size_t)r0 * DF;
        const int col = lane << 2;
        const uint4 t0 = *(const uint4*)(src + (size_t)(w      ) * DF + col);
        const uint4 t1 = *(const uint4*)(src + (size_t)(w + 32 ) * DF + col);
        const uint4 t2 = *(const uint4*)(src + (size_t)(w + 64 ) * DF + col);
        const uint4 t3 = *(const uint4*)(src + (size_t)(w + 96 ) * DF + col);
        *(uint4*)&xsm[(size_t)(w      ) * DF + col] = t0;
        *(uint4*)&xsm[(size_t)(w + 32 ) * DF + col] = t1;
        *(uint4*)&xsm[(size_t)(w + 64 ) * DF + col] = t2;
        *(uint4*)&xsm[(size_t)(w + 96 ) * DF + col] = t3;
    }

    // dcnt is warp-uniform (popc of full ballots)
#pragma unroll
    for (int rp = 0; rp < 4; ++rp) {
        const int r = (w << 2) + rp;
        const float d = (float)dcnt[rp];
        const float inv = (dcnt[rp] > 0) ? (1.0f / d) : 0.0f;
        float4 zv;
        zv.x = acc[rp][0] * inv; zv.y = acc[rp][1] * inv;
        zv.z = acc[rp][2] * inv; zv.w = acc[rp][3] * inv;
        *reinterpret_cast<float4*>(&zsm[(size_t)r * ZS + (lane << 2)]) = zv;
        if (lane == 0) degs[r] = d;
    }
    __syncthreads();

    // -------- phase 2: out = xsm @ Wa + zsm @ Wb  (k-pair packed f32x2) --------
    const int rg  = w >> 2;                 // 0..7 -> rows 16*rg .. +16
    const int col = ((w & 3) << 5) + lane;  // 0..127

    unsigned long long cacc[16];
#pragma unroll
    for (int i = 0; i < 16; ++i) cacc[i] = 0ull;

#pragma unroll 1
    for (int pass = 0; pass < 2; ++pass) {
        const float* A  = pass ? zsm : xsm;
        const int    As = pass ? ZS : DF;
        const float* Wp = pass ? g_Wbp : g_Wap;
#pragma unroll 4
        for (int k = 0; k < DF; k += 4) {
            const unsigned long long w0 = *reinterpret_cast<const unsigned long long*>(
                &Wp[(size_t)(k >> 1) * 256 + (col << 1)]);
            const unsigned long long w1 = *reinterpret_cast<const unsigned long long*>(
                &Wp[(size_t)((k >> 1) + 1) * 256 + (col << 1)]);
#pragma unroll
            for (int i = 0; i < 16; ++i) {
                const ulonglong2 av = *reinterpret_cast<const ulonglong2*>(
                    &A[(size_t)(16 * rg + i) * As + k]);   // warp-uniform broadcast
                fma2(cacc[i], av.x, w0);
                fma2(cacc[i], av.y, w1);
            }
        }
    }

    float* outb = out + ((size_t)b * NNODE + r0) * UNITS;
#pragma unroll
    for (int i = 0; i < 16; ++i) {
        const int r = 16 * rg + i;
        unsigned lo, hi;
        asm("mov.b64 {%0, %1}, %2;" : "=r"(lo), "=r"(hi) : "l"(cacc[i]));
        float o = __uint_as_float(lo) + __uint_as_float(hi);

        if (degs[r] == 0.0f) {
            // message term must be exactly zero: remove the x@Wr@W2 contribution
            float corr = 0.0f;
            for (int k = 0; k < DF; ++k)
                corr = fmaf(xsm[(size_t)r * DF + k], g_Wr2[k * UNITS + col], corr);
            o -= corr;
        }
        outb[(size_t)r * UNITS + col] = o;
    }
}

// ---------------------------------------------------------------------------
// Launch
// ---------------------------------------------------------------------------
extern "C" void kernel_launch(void* const* d_in, const int* in_sizes, int n_in,
                              void* d_out, int out_size) {
    (void)in_sizes; (void)n_in; (void)out_size;
    const float* x    = (const float*)d_in[0];
    const float* adj  = (const float*)d_in[1];
    const float* Wmsg = (const float*)d_in[2];
    const float* Wupd = (const float*)d_in[3];
    float* out = (float*)d_out;

    prep_weights<<<128, 128>>>(Wmsg, Wupd);

    const size_t shbytes = (size_t)2 * ADJ_ST_FLOATS * sizeof(float);  // 135168
    cudaFuncSetAttribute(mpnn_main, cudaFuncAttributeMaxDynamicSharedMemorySize,
                         (int)shbytes);
    mpnn_main<<<dim3(NNODE / TILE_R, BATCH), 1024, shbytes>>>(x, adj, out);
}